// round 13
// baseline (speedup 1.0000x reference)
#include <cuda_runtime.h>
#include <cuda_fp16.h>
#include <cstdint>
#include <math.h>

#define CIN 64
#define COUT 256
#define DD 31
#define HH 96
#define WW 96
#define HW (HH*WW)
#define DHW (DD*HW)
#define EPS 1e-5f

#define THREADS 128

// padded transposed x: [33][98] planes of [8 ci-chunk][104 w][16B]
#define XT_D 33
#define XT_H 98
#define XT_W 104
#define PLANE_BYTES (8*XT_W*16)          // 13312
__device__ __half g_xt[(size_t)XT_D * XT_H * PLANE_BYTES / 2];

__device__ float  g_gates[(size_t)COUT * DHW];   // activated gates [cout][d][h][w]
// weights: [tap][2 coutgroup][8 ci-chunk][128 cout][8 ci] fp16 -> 16KB per (tap,group)
__device__ __half g_wth[27 * COUT * CIN];

// smem: A 2-stage ring of 16KB, then B ring of 4 planes
// B plane: [8 chunk][136 row(4he x 34we)][16B] = 17408 B
#define SMA_BYTES 16384
#define NSTAGE 2
#define SMB_OFF (NSTAGE*SMA_BYTES)               // 32768
#define BP_CHUNK_STRIDE (136*16)                 // 2176
#define BP_BYTES (8*BP_CHUNK_STRIDE)             // 17408
#define SMEM_TOTAL (SMB_OFF + 4*BP_BYTES)        // 102400 -> 2 CTAs/SM

#define NTAP_TOTAL (31*27)                       // 837 A stages

__device__ __forceinline__ uint32_t cvta_s(const void* p) {
    uint32_t a;
    asm("{ .reg .u64 t; cvta.to.shared.u64 t, %1; cvt.u32.u64 %0, t; }" : "=r"(a) : "l"(p));
    return a;
}
__device__ __forceinline__ float fast_tanh(float x) {
    float y; asm("tanh.approx.f32 %0, %1;" : "=f"(y) : "f"(x)); return y;
}
__device__ __forceinline__ void ldsm_x4(uint32_t& r0, uint32_t& r1, uint32_t& r2, uint32_t& r3,
                                        uint32_t addr) {
    asm volatile("ldmatrix.sync.aligned.m8n8.x4.shared.b16 {%0,%1,%2,%3}, [%4];"
        : "=r"(r0), "=r"(r1), "=r"(r2), "=r"(r3) : "r"(addr));
}
#define MBAR_INIT(mbar, count) \
    asm volatile("mbarrier.init.shared.b64 [%0], %1;" :: "r"((uint32_t)(mbar)), "r"((uint32_t)(count)) : "memory")
#define MBAR_EXPECT_TX(mbar, bytes) \
    asm volatile("mbarrier.arrive.expect_tx.shared.b64 _, [%0], %1;" \
        :: "r"((uint32_t)(mbar)), "r"((uint32_t)(bytes)) : "memory")
#define MBAR_ARRIVE(mbar) \
    asm volatile("mbarrier.arrive.shared.b64 _, [%0];" :: "r"((uint32_t)(mbar)) : "memory")
#define MBAR_WAIT(mbar, parity) do { \
    uint32_t _m = (uint32_t)(mbar); uint32_t _p = (uint32_t)(parity); uint32_t _done; \
    asm volatile("{\n\t.reg .pred p;\n\tmbarrier.try_wait.parity.acquire.cta.shared::cta.b64 p, [%1], %2;\n\tselp.b32 %0, 1, 0, p;\n\t}" \
        : "=r"(_done) : "r"(_m), "r"(_p) : "memory"); \
    if (!_done) { \
        asm volatile("{\n\t.reg .pred P1;\n\tWL_%=:\n\tmbarrier.try_wait.parity.acquire.cta.shared::cta.b64 P1, [%0], %1, 0x989680;\n\t@P1 bra.uni WD_%=;\n\tbra.uni WL_%=;\n\tWD_%=:\n\t}" \
            :: "r"(_m), "r"(_p) : "memory"); \
    } } while (0)
#define BULK_G2S(dst, src, bytes, mbar) \
    asm volatile("cp.async.bulk.shared::cluster.global.mbarrier::complete_tx::bytes [%0], [%1], %2, [%3];" \
        :: "r"((uint32_t)(dst)), "l"(src), "r"((uint32_t)(bytes)), "r"((uint32_t)(mbar)) : "memory")

// ---------------- pre-pass kernels ----------------
__global__ void zero_xt_kernel() {
    size_t i = (size_t)blockIdx.x * blockDim.x + threadIdx.x;
    float4* p = reinterpret_cast<float4*>(g_xt);
    if (i < ((size_t)XT_D * XT_H * PLANE_BYTES) / 16) p[i] = make_float4(0.f, 0.f, 0.f, 0.f);
}

// x[ci][d][h][w] f32 -> plane(d+1,h+1): [chunk][w+1][16B] fp16
__global__ void transpose_x_kernel(const float* __restrict__ x) {
    const int d = blockIdx.y, h = blockIdx.x;
    const int w = threadIdx.x;
    if (w >= WW) return;
    const float* src = x + (size_t)d * HW + h * WW + w;
    uint32_t pk[32];
#pragma unroll
    for (int j = 0; j < 32; ++j) {
        float v0 = src[(size_t)(2 * j) * DHW];
        float v1 = src[(size_t)(2 * j + 1) * DHW];
        __half2 h2 = __float22half2_rn(make_float2(v0, v1));
        pk[j] = *reinterpret_cast<uint32_t*>(&h2);
    }
    char* plane = (char*)g_xt + ((size_t)(d + 1) * XT_H + (h + 1)) * PLANE_BYTES;
#pragma unroll
    for (int c = 0; c < 8; ++c) {
        uint4 q = make_uint4(pk[c * 4], pk[c * 4 + 1], pk[c * 4 + 2], pk[c * 4 + 3]);
        *reinterpret_cast<uint4*>(plane + c * (XT_W * 16) + (w + 1) * 16) = q;
    }
}

// w[cout][cin][27] -> g_wth[tap][zg][chunk][cout_local 128][8 ci]
__global__ void repack_kernel(const float* __restrict__ w) {
    int id = blockIdx.x * blockDim.x + threadIdx.x;
    if (id >= COUT * CIN) return;
    int cout = id >> 6, cin = id & 63;
    const float* src = w + (size_t)id * 27;
    const int zg = cout >> 7, cl = cout & 127;
    const int chunk = cin >> 3, ci7 = cin & 7;
    const size_t base = ((size_t)zg * 8192) + chunk * 1024 + cl * 8 + ci7;
#pragma unroll
    for (int t = 0; t < 27; ++t)
        g_wth[(size_t)t * 16384 + base] = __float2half_rn(src[t]);
}

// ---------------- conv + BN + activation (persistent over d) ----------------
__global__ __launch_bounds__(THREADS, 2)
void conv_mma_kernel(const float* __restrict__ gamma, const float* __restrict__ beta,
                     const float* __restrict__ mean, const float* __restrict__ var)
{
    extern __shared__ __align__(128) char smem[];
    __shared__ __align__(8) uint64_t mbars[NSTAGE * 2 + 4];   // Ardy[2], Afree[2], Bp[4]
    const uint32_t smA_u = cvta_s(smem);
    const uint32_t smB_u = smA_u + SMB_OFF;
    uint32_t mbArdy[NSTAGE], mbAfree[NSTAGE], mbBp[4];
#pragma unroll
    for (int i = 0; i < NSTAGE; ++i) { mbArdy[i] = cvta_s(&mbars[i]); mbAfree[i] = cvta_s(&mbars[NSTAGE + i]); }
#pragma unroll
    for (int i = 0; i < 4; ++i) mbBp[i] = cvta_s(&mbars[2 * NSTAGE + i]);

    const int tid = threadIdx.x, wid = tid >> 5, lane = tid & 31;
    const int zg = blockIdx.y;
    const int coutBase = zg * 128;
    const int hBase = (blockIdx.x / 3) * 2, wBase = (blockIdx.x % 3) * 32;

    const char* wsrc = (const char*)g_wth + (size_t)zg * SMA_BYTES;

    // 4 warps: 2 along M (64), 2 along N (32)
    const int warpM = (wid >> 1) * 64, warpN = (wid & 1) * 32;
    const int mr = lane >> 2, nc = lane & 3;
    const int matsel = lane >> 3, rl = lane & 7;
    const int mhalf = matsel & 1, khalf = matsel >> 1;

    // A addr = aBase[f] + buf*16384 + s*4096
    uint32_t aBase[4];
#pragma unroll
    for (int f = 0; f < 4; ++f)
        aBase[f] = smA_u + khalf * 2048 + (warpM + 16 * f + mhalf * 8 + rl) * 16;
    // B addr = bBase[g2] + slot*BP_BYTES + tapOff*16 + s*4352
    uint32_t bBase[2];
#pragma unroll
    for (int g2 = 0; g2 < 2; ++g2) {
        int n = warpN + g2 * 16 + mhalf * 8 + rl;
        bBase[g2] = smB_u + khalf * BP_CHUNK_STRIDE + ((n >> 5) * 34 + (n & 31)) * 16;
    }

    if (tid == 0) {
#pragma unroll
        for (int i = 0; i < NSTAGE; ++i) { MBAR_INIT(mbArdy[i], 1); MBAR_INIT(mbAfree[i], 4); }
#pragma unroll
        for (int i = 0; i < 4; ++i) MBAR_INIT(mbBp[i], 1);
    }
    __syncthreads();
    if (tid == 0) {
#pragma unroll
        for (int i = 0; i < 3; ++i) MBAR_EXPECT_TX(mbBp[i], (uint32_t)BP_BYTES);
        // A stages 0,1
#pragma unroll
        for (int t = 0; t < NSTAGE; ++t) MBAR_EXPECT_TX(mbArdy[t], SMA_BYTES);
    }
    __syncthreads();

    // prologue: B planes 0,1,2 (96 copies of 544B) + A stages 0,1
    if (tid < 96) {
        const int p = tid / 32, r2 = tid % 32;
        const int he = r2 / 8, chunk = r2 % 8;
        const char* src = (const char*)g_xt
            + ((size_t)p * XT_H + hBase + he) * PLANE_BYTES
            + chunk * (XT_W * 16) + wBase * 16;
        BULK_G2S(smB_u + p * BP_BYTES + chunk * BP_CHUNK_STRIDE + he * (34 * 16),
                 src, 544u, mbBp[p]);
    }
    if (tid == 0) {
#pragma unroll
        for (int t = 0; t < NSTAGE; ++t)
            BULK_G2S(smA_u + t * SMA_BYTES, wsrc + (size_t)t * 2 * SMA_BYTES,
                     SMA_BYTES, mbArdy[t]);
    }

    float acc[4][4][4];
#pragma unroll
    for (int f = 0; f < 4; ++f)
#pragma unroll
        for (int g = 0; g < 4; ++g)
#pragma unroll
            for (int c = 0; c < 4; ++c) acc[f][g][c] = 0.0f;

    int t = 0;   // global A stage counter = d*27 + tap
    for (int d = 0; d < DD; ++d) {
        // wait B planes (d..d+2); inductively only d+2 is new (d=0 waits all 3)
        if (d == 0) { MBAR_WAIT(mbBp[0], 0); MBAR_WAIT(mbBp[1], 0); }
        {
            const int p = d + 2;
            MBAR_WAIT(mbBp[p & 3], (p >> 2) & 1);
        }
        // prefetch plane d+3 (slot held plane d-1, done since last d's sync)
        if (tid < 32 && d + 3 <= 32) {
            const int p = d + 3;
            if (lane == 0) MBAR_EXPECT_TX(mbBp[p & 3], (uint32_t)BP_BYTES);
            __syncwarp();
            const int he = lane / 8, chunk = lane % 8;
            const char* src = (const char*)g_xt
                + ((size_t)p * XT_H + hBase + he) * PLANE_BYTES
                + chunk * (XT_W * 16) + wBase * 16;
            BULK_G2S(smB_u + (p & 3) * BP_BYTES + chunk * BP_CHUNK_STRIDE + he * (34 * 16),
                     src, 544u, mbBp[p & 3]);
        }

        for (int tap = 0; tap < 27; ++tap, ++t) {
            const int kd = tap / 9, kh = (tap / 3) % 3, kw = tap % 3;
            const int buf = t & 1;
            MBAR_WAIT(mbArdy[buf], (t >> 1) & 1);

            const uint32_t aOff = (uint32_t)buf * SMA_BYTES;
            const uint32_t bOff = (uint32_t)((d + kd) & 3) * BP_BYTES
                                + (uint32_t)(kh * 34 + kw) * 16;
#pragma unroll
            for (int s = 0; s < 4; ++s) {
                uint32_t a[4][4];
#pragma unroll
                for (int f = 0; f < 4; ++f)
                    ldsm_x4(a[f][0], a[f][1], a[f][2], a[f][3],
                            aBase[f] + aOff + s * 4096);
                uint32_t b[4][2];
#pragma unroll
                for (int g2 = 0; g2 < 2; ++g2)
                    ldsm_x4(b[2 * g2][0], b[2 * g2 + 1][0],
                            b[2 * g2][1], b[2 * g2 + 1][1],
                            bBase[g2] + bOff + s * 4352);
#pragma unroll
                for (int f = 0; f < 4; ++f)
#pragma unroll
                    for (int g = 0; g < 4; ++g) {
                        asm volatile(
                            "mma.sync.aligned.m16n8k16.row.col.f32.f16.f16.f32 "
                            "{%0,%1,%2,%3}, {%4,%5,%6,%7}, {%8,%9}, {%0,%1,%2,%3};"
                            : "+f"(acc[f][g][0]), "+f"(acc[f][g][1]),
                              "+f"(acc[f][g][2]), "+f"(acc[f][g][3])
                            : "r"(a[f][0]), "r"(a[f][1]), "r"(a[f][2]), "r"(a[f][3]),
                              "r"(b[g][0]), "r"(b[g][1]));
                    }
            }
            if (lane == 0) MBAR_ARRIVE(mbAfree[buf]);
            if (tid == 0) {
                const int nt = t + NSTAGE;
                if (nt < NTAP_TOTAL) {
                    const int nb = nt & 1;
                    MBAR_WAIT(mbAfree[nb], ((nt >> 1) - 1) & 1);
                    MBAR_EXPECT_TX(mbArdy[nb], SMA_BYTES);
                    BULK_G2S(smA_u + nb * SMA_BYTES,
                             wsrc + (size_t)(nt % 27) * 2 * SMA_BYTES, SMA_BYTES, mbArdy[nb]);
                }
            }
        }
        __syncthreads();   // all warps done with planes d..d+2 before next prefetch cycle

        // ---- epilogue for this d: BN + activation + STG, reset acc
#pragma unroll
        for (int f = 0; f < 4; ++f)
#pragma unroll
            for (int r = 0; r < 2; ++r) {
                const int cg = coutBase + warpM + 16 * f + 8 * r + mr;
                const float s = gamma[cg] * rsqrtf(var[cg] + EPS);
                const float sh = beta[cg] - mean[cg] * s;
                const int gt = cg >> 6;
                const bool sg = (gt == 1) || (gt == 2);
                float* orow = g_gates + (size_t)cg * DHW + (size_t)d * HW;
#pragma unroll
                for (int g = 0; g < 4; ++g) {
                    const int n0 = warpN + 8 * g + 2 * nc;
                    const int h2 = n0 >> 5, w2 = n0 & 31;
                    float v0 = acc[f][g][2 * r + 0] * s + sh;
                    float v1 = acc[f][g][2 * r + 1] * s + sh;
                    if (sg) {
                        v0 = 0.5f * fast_tanh(0.5f * v0) + 0.5f;
                        v1 = 0.5f * fast_tanh(0.5f * v1) + 0.5f;
                    } else {
                        v0 = fast_tanh(v0);
                        v1 = fast_tanh(v1);
                    }
                    *reinterpret_cast<float2*>(orow + (hBase + h2) * WW + wBase + w2)
                        = make_float2(v0, v1);
                }
            }
#pragma unroll
        for (int f = 0; f < 4; ++f)
#pragma unroll
            for (int g = 0; g < 4; ++g)
#pragma unroll
                for (int c = 0; c < 4; ++c) acc[f][g][c] = 0.0f;
    }
}

// ---------------- SRU scan over depth ----------------
__global__ void sru_scan_kernel(float* __restrict__ out)
{
    const int idx = blockIdx.x * blockDim.x + threadIdx.x;
    if (idx >= CIN * HW) return;
    const int c = idx / HW;
    const int hw = idx % HW;

    const float* pw = g_gates + (size_t)(0 * 64 + c) * DHW + hw;
    const float* pf = g_gates + (size_t)(1 * 64 + c) * DHW + hw;
    const float* pr = g_gates + (size_t)(2 * 64 + c) * DHW + hw;
    const float* px = g_gates + (size_t)(3 * 64 + c) * DHW + hw;
    float* po = out + (size_t)c * DHW + hw;

    float f = pf[0], r = pr[0], xx = px[0];
    float C = 1.0f - f;
    po[0] = r * C + (1.0f - r) * xx;

    for (int dd = 1; dd < DD; ++dd) {
        const int off = dd * HW;
        const float wv = pw[off];
        f = pf[off]; r = pr[off]; xx = px[off];
        C = f * C + (1.0f - f) * wv;
        po[off] = r * C + (1.0f - r) * xx;
    }
}

extern "C" void kernel_launch(void* const* d_in, const int* in_sizes, int n_in,
                              void* d_out, int out_size)
{
    const float* x     = (const float*)d_in[0];
    const float* w     = (const float*)d_in[1];
    const float* gamma = (const float*)d_in[2];
    const float* beta  = (const float*)d_in[3];
    const float* mean  = (const float*)d_in[4];
    const float* var   = (const float*)d_in[5];
    float* out = (float*)d_out;

    const size_t xt_vec = ((size_t)XT_D * XT_H * PLANE_BYTES) / 16;
    zero_xt_kernel<<<(int)((xt_vec + 255) / 256), 256>>>();
    transpose_x_kernel<<<dim3(HH, DD), 128>>>(x);
    repack_kernel<<<64, 256>>>(w);

    cudaFuncSetAttribute(conv_mma_kernel,
                         cudaFuncAttributeMaxDynamicSharedMemorySize, SMEM_TOTAL);
    dim3 grid(144, 2);    // (48 h-tiles x 3 w-tiles), cout-groups; d looped inside
    conv_mma_kernel<<<grid, THREADS, SMEM_TOTAL>>>(gamma, beta, mean, var);

    const int scan_threads = 256;
    const int scan_blocks = (CIN * HW + scan_threads - 1) / scan_threads;
    sru_scan_kernel<<<scan_blocks, scan_threads>>>(out);
}

// round 14
// speedup vs baseline: 1.2214x; 1.2214x over previous
#include <cuda_runtime.h>
#include <cuda_fp16.h>
#include <cstdint>
#include <math.h>

#define CIN 64
#define COUT 256
#define DD 31
#define HH 96
#define WW 96
#define HW (HH*WW)
#define DHW (DD*HW)
#define EPS 1e-5f

#define BH 4
#define BW 32

// padded transposed x: [33][98] planes of [8 ci-chunk][104 w][16B]
#define XT_D 33
#define XT_H 98
#define XT_W 104
#define PLANE_BYTES (8*XT_W*16)          // 13312
__device__ __half g_xt[(size_t)XT_D * XT_H * PLANE_BYTES / 2];

__device__ __half g_gates[(size_t)COUT * DHW];   // activated gates [cout][d][h][w] fp16
// weights: [tap][2 coutgroup][8 ci-chunk][128 cout][8 ci] fp16 -> 16KB per (tap,group)
__device__ __half g_wth[27 * COUT * CIN];

// smem: A 2-stage ring of 16KB, then B [8 chunk][612 row][16B]
#define SMA_BYTES 16384
#define NSTAGE 2
#define SMB_OFF (NSTAGE*SMA_BYTES)               // 32768
#define B_ROWS 612                               // 3 dz * 6 he * 34 we
#define B_CHUNK_STRIDE (B_ROWS*16)               // 9792
#define SMEM_TOTAL (SMB_OFF + 8*B_CHUNK_STRIDE)  // 111104 (108.5 KB) -> 2 CTAs/SM

__device__ __forceinline__ uint32_t cvta_s(const void* p) {
    uint32_t a;
    asm("{ .reg .u64 t; cvta.to.shared.u64 t, %1; cvt.u32.u64 %0, t; }" : "=r"(a) : "l"(p));
    return a;
}
__device__ __forceinline__ float fast_tanh(float x) {
    float y; asm("tanh.approx.f32 %0, %1;" : "=f"(y) : "f"(x)); return y;
}
__device__ __forceinline__ void ldsm_x4(uint32_t& r0, uint32_t& r1, uint32_t& r2, uint32_t& r3,
                                        uint32_t addr) {
    asm volatile("ldmatrix.sync.aligned.m8n8.x4.shared.b16 {%0,%1,%2,%3}, [%4];"
        : "=r"(r0), "=r"(r1), "=r"(r2), "=r"(r3) : "r"(addr));
}
#define MBAR_INIT(mbar, count) \
    asm volatile("mbarrier.init.shared.b64 [%0], %1;" :: "r"((uint32_t)(mbar)), "r"((uint32_t)(count)) : "memory")
#define MBAR_EXPECT_TX(mbar, bytes) \
    asm volatile("mbarrier.arrive.expect_tx.shared.b64 _, [%0], %1;" \
        :: "r"((uint32_t)(mbar)), "r"((uint32_t)(bytes)) : "memory")
#define MBAR_ARRIVE(mbar) \
    asm volatile("mbarrier.arrive.shared.b64 _, [%0];" :: "r"((uint32_t)(mbar)) : "memory")
#define MBAR_WAIT(mbar, parity) do { \
    uint32_t _m = (uint32_t)(mbar); uint32_t _p = (uint32_t)(parity); uint32_t _done; \
    asm volatile("{\n\t.reg .pred p;\n\tmbarrier.try_wait.parity.acquire.cta.shared::cta.b64 p, [%1], %2;\n\tselp.b32 %0, 1, 0, p;\n\t}" \
        : "=r"(_done) : "r"(_m), "r"(_p) : "memory"); \
    if (!_done) { \
        asm volatile("{\n\t.reg .pred P1;\n\tWL_%=:\n\tmbarrier.try_wait.parity.acquire.cta.shared::cta.b64 P1, [%0], %1, 0x989680;\n\t@P1 bra.uni WD_%=;\n\tbra.uni WL_%=;\n\tWD_%=:\n\t}" \
            :: "r"(_m), "r"(_p) : "memory"); \
    } } while (0)
#define BULK_G2S(dst, src, bytes, mbar) \
    asm volatile("cp.async.bulk.shared::cluster.global.mbarrier::complete_tx::bytes [%0], [%1], %2, [%3];" \
        :: "r"((uint32_t)(dst)), "l"(src), "r"((uint32_t)(bytes)), "r"((uint32_t)(mbar)) : "memory")

// ---------------- pre-pass kernels ----------------
__global__ void zero_xt_kernel() {
    size_t i = (size_t)blockIdx.x * blockDim.x + threadIdx.x;
    float4* p = reinterpret_cast<float4*>(g_xt);
    if (i < ((size_t)XT_D * XT_H * PLANE_BYTES) / 16) p[i] = make_float4(0.f, 0.f, 0.f, 0.f);
}

// x[ci][d][h][w] f32 -> plane(d+1,h+1): [chunk][w+1][16B] fp16
__global__ void transpose_x_kernel(const float* __restrict__ x) {
    const int d = blockIdx.y, h = blockIdx.x;
    const int w = threadIdx.x;
    if (w >= WW) return;
    const float* src = x + (size_t)d * HW + h * WW + w;
    uint32_t pk[32];
#pragma unroll
    for (int j = 0; j < 32; ++j) {
        float v0 = src[(size_t)(2 * j) * DHW];
        float v1 = src[(size_t)(2 * j + 1) * DHW];
        __half2 h2 = __float22half2_rn(make_float2(v0, v1));
        pk[j] = *reinterpret_cast<uint32_t*>(&h2);
    }
    char* plane = (char*)g_xt + ((size_t)(d + 1) * XT_H + (h + 1)) * PLANE_BYTES;
#pragma unroll
    for (int c = 0; c < 8; ++c) {
        uint4 q = make_uint4(pk[c * 4], pk[c * 4 + 1], pk[c * 4 + 2], pk[c * 4 + 3]);
        *reinterpret_cast<uint4*>(plane + c * (XT_W * 16) + (w + 1) * 16) = q;
    }
}

// w[cout][cin][27] -> g_wth[tap][zg][chunk][cout_local 128][8 ci]
__global__ void repack_kernel(const float* __restrict__ w) {
    int id = blockIdx.x * blockDim.x + threadIdx.x;
    if (id >= COUT * CIN) return;
    int cout = id >> 6, cin = id & 63;
    const float* src = w + (size_t)id * 27;
    const int zg = cout >> 7, cl = cout & 127;
    const int chunk = cin >> 3, ci7 = cin & 7;
    const size_t base = ((size_t)zg * 8192) + chunk * 1024 + cl * 8 + ci7;
#pragma unroll
    for (int t = 0; t < 27; ++t)
        g_wth[(size_t)t * 16384 + base] = __float2half_rn(src[t]);
}

// ---------------- conv + BN + activation ----------------
__global__ __launch_bounds__(256, 2)
void conv_mma_kernel(const float* __restrict__ gamma, const float* __restrict__ beta,
                     const float* __restrict__ mean, const float* __restrict__ var)
{
    extern __shared__ __align__(128) char smem[];
    __shared__ __align__(8) uint64_t mbars[NSTAGE * 2 + 3];   // Ardy[2], Afree[2], B[3]
    const uint32_t smA_u = cvta_s(smem);
    const uint32_t smB_u = smA_u + SMB_OFF;
    uint32_t mbArdy[NSTAGE], mbAfree[NSTAGE], mbB[3];
#pragma unroll
    for (int i = 0; i < NSTAGE; ++i) { mbArdy[i] = cvta_s(&mbars[i]); mbAfree[i] = cvta_s(&mbars[NSTAGE + i]); }
#pragma unroll
    for (int i = 0; i < 3; ++i) mbB[i] = cvta_s(&mbars[2 * NSTAGE + i]);

    const int tid = threadIdx.x, wid = tid >> 5, lane = tid & 31;
    const int d = blockIdx.y;
    const int zg = blockIdx.z;
    const int coutBase = zg * 128;
    const int hBase = (blockIdx.x / 3) * BH, wBase = (blockIdx.x % 3) * BW;

    const char* wsrc = (const char*)g_wth + (size_t)zg * SMA_BYTES;

    // 8 warps: 4 along M (32 each), 2 along N (64 each)
    const int warpM = (wid >> 1) * 32, warpN = (wid & 1) * 64;
    const int mr = lane >> 2, nc = lane & 3;
    const int matsel = lane >> 3, rl = lane & 7;
    const int mhalf = matsel & 1, khalf = matsel >> 1;

    uint32_t aBase[2];
#pragma unroll
    for (int f = 0; f < 2; ++f)
        aBase[f] = smA_u + khalf * 2048 + (warpM + 16 * f + mhalf * 8 + rl) * 16;
    uint32_t bBase[4];
#pragma unroll
    for (int g2 = 0; g2 < 4; ++g2) {
        int n = warpN + g2 * 16 + mhalf * 8 + rl;
        bBase[g2] = smB_u + khalf * B_CHUNK_STRIDE + ((n >> 5) * 34 + (n & 31)) * 16;
    }

    if (tid == 0) {
#pragma unroll
        for (int i = 0; i < NSTAGE; ++i) { MBAR_INIT(mbArdy[i], 1); MBAR_INIT(mbAfree[i], 8); }
#pragma unroll
        for (int i = 0; i < 3; ++i) MBAR_INIT(mbB[i], 1);
    }
    __syncthreads();
    if (tid == 0) {
#pragma unroll
        for (int i = 0; i < 3; ++i) MBAR_EXPECT_TX(mbB[i], 48u * 544u);
    }
    __syncthreads();

    // ---- B: 144 copies of 544B, one per thread (dzl, he, chunk)
    if (tid < 144) {
        const int dzl = tid / 48, r2 = tid % 48;
        const int he = r2 / 8, chunk = r2 % 8;
        const char* src = (const char*)g_xt
            + ((size_t)(d + dzl) * XT_H + hBase + he) * PLANE_BYTES
            + chunk * (XT_W * 16) + wBase * 16;
        BULK_G2S(smB_u + chunk * B_CHUNK_STRIDE + (dzl * 204 + he * 34) * 16,
                 src, 544u, mbB[dzl]);
    }
    // ---- A taps 0..1
    if (tid == 0) {
#pragma unroll
        for (int t = 0; t < NSTAGE; ++t) {
            MBAR_EXPECT_TX(mbArdy[t], SMA_BYTES);
            BULK_G2S(smA_u + t * SMA_BYTES, wsrc + (size_t)t * 2 * SMA_BYTES,
                     SMA_BYTES, mbArdy[t]);
        }
    }

    float acc[2][8][4];
#pragma unroll
    for (int f = 0; f < 2; ++f)
#pragma unroll
        for (int g = 0; g < 8; ++g)
#pragma unroll
            for (int c = 0; c < 4; ++c) acc[f][g][c] = 0.0f;

    for (int tap = 0; tap < 27; ++tap) {
        const int kd = tap / 9, kh = (tap / 3) % 3, kw = tap % 3;
        if (kh == 0 && kw == 0) { MBAR_WAIT(mbB[kd], 0); }
        const int buf = tap % NSTAGE;
        MBAR_WAIT(mbArdy[buf], (tap / NSTAGE) & 1);

        const uint32_t aOff = (uint32_t)buf * SMA_BYTES;
        const uint32_t bOff = (uint32_t)(kd * 204 + kh * 34 + kw) * 16;
#pragma unroll
        for (int s = 0; s < 4; ++s) {
            uint32_t a[2][4];
#pragma unroll
            for (int f = 0; f < 2; ++f)
                ldsm_x4(a[f][0], a[f][1], a[f][2], a[f][3],
                        aBase[f] + aOff + s * 4096);
            uint32_t b[8][2];
#pragma unroll
            for (int g2 = 0; g2 < 4; ++g2)
                ldsm_x4(b[2 * g2][0], b[2 * g2 + 1][0],
                        b[2 * g2][1], b[2 * g2 + 1][1],
                        bBase[g2] + bOff + s * (2 * B_CHUNK_STRIDE));
#pragma unroll
            for (int f = 0; f < 2; ++f)
#pragma unroll
                for (int g = 0; g < 8; ++g) {
                    asm volatile(
                        "mma.sync.aligned.m16n8k16.row.col.f32.f16.f16.f32 "
                        "{%0,%1,%2,%3}, {%4,%5,%6,%7}, {%8,%9}, {%0,%1,%2,%3};"
                        : "+f"(acc[f][g][0]), "+f"(acc[f][g][1]),
                          "+f"(acc[f][g][2]), "+f"(acc[f][g][3])
                        : "r"(a[f][0]), "r"(a[f][1]), "r"(a[f][2]), "r"(a[f][3]),
                          "r"(b[g][0]), "r"(b[g][1]));
                }
        }
        if (lane == 0) MBAR_ARRIVE(mbAfree[buf]);
        if (tid == 0) {
            const int nt = tap + NSTAGE;
            if (nt < 27) {
                const int nb = nt % NSTAGE;
                MBAR_WAIT(mbAfree[nb], (nt / NSTAGE - 1) & 1);
                MBAR_EXPECT_TX(mbArdy[nb], SMA_BYTES);
                BULK_G2S(smA_u + nb * SMA_BYTES,
                         wsrc + (size_t)nt * 2 * SMA_BYTES, SMA_BYTES, mbArdy[nb]);
            }
        }
    }

    // ---- epilogue: BN + activation + STG (__half2)
#pragma unroll
    for (int f = 0; f < 2; ++f)
#pragma unroll
        for (int r = 0; r < 2; ++r) {
            const int cg = coutBase + warpM + 16 * f + 8 * r + mr;
            const float s = gamma[cg] * rsqrtf(var[cg] + EPS);
            const float sh = beta[cg] - mean[cg] * s;
            const int gt = cg >> 6;
            const bool sg = (gt == 1) || (gt == 2);
            __half* orow = g_gates + (size_t)cg * DHW + (size_t)d * HW;
#pragma unroll
            for (int g = 0; g < 8; ++g) {
                const int n0 = warpN + 8 * g + 2 * nc;
                const int h2 = n0 >> 5, w2 = n0 & 31;
                float v0 = acc[f][g][2 * r + 0] * s + sh;
                float v1 = acc[f][g][2 * r + 1] * s + sh;
                if (sg) {
                    v0 = 0.5f * fast_tanh(0.5f * v0) + 0.5f;
                    v1 = 0.5f * fast_tanh(0.5f * v1) + 0.5f;
                } else {
                    v0 = fast_tanh(v0);
                    v1 = fast_tanh(v1);
                }
                *reinterpret_cast<__half2*>(orow + (hBase + h2) * WW + wBase + w2)
                    = __float22half2_rn(make_float2(v0, v1));
            }
        }
}

// ---------------- SRU scan over depth (fp16 gates -> f32 out) ----------------
__global__ void sru_scan_kernel(float* __restrict__ out)
{
    const int idx = blockIdx.x * blockDim.x + threadIdx.x;
    if (idx >= CIN * HW) return;
    const int c = idx / HW;
    const int hw = idx % HW;

    const __half* pw = g_gates + (size_t)(0 * 64 + c) * DHW + hw;
    const __half* pf = g_gates + (size_t)(1 * 64 + c) * DHW + hw;
    const __half* pr = g_gates + (size_t)(2 * 64 + c) * DHW + hw;
    const __half* px = g_gates + (size_t)(3 * 64 + c) * DHW + hw;
    float* po = out + (size_t)c * DHW + hw;

    float f = __half2float(pf[0]);
    float r = __half2float(pr[0]);
    float xx = __half2float(px[0]);
    float C = 1.0f - f;
    po[0] = r * C + (1.0f - r) * xx;

    for (int dd = 1; dd < DD; ++dd) {
        const int off = dd * HW;
        const float wv = __half2float(pw[off]);
        f = __half2float(pf[off]);
        r = __half2float(pr[off]);
        xx = __half2float(px[off]);
        C = f * C + (1.0f - f) * wv;
        po[off] = r * C + (1.0f - r) * xx;
    }
}

extern "C" void kernel_launch(void* const* d_in, const int* in_sizes, int n_in,
                              void* d_out, int out_size)
{
    const float* x     = (const float*)d_in[0];
    const float* w     = (const float*)d_in[1];
    const float* gamma = (const float*)d_in[2];
    const float* beta  = (const float*)d_in[3];
    const float* mean  = (const float*)d_in[4];
    const float* var   = (const float*)d_in[5];
    float* out = (float*)d_out;

    const size_t xt_vec = ((size_t)XT_D * XT_H * PLANE_BYTES) / 16;
    zero_xt_kernel<<<(int)((xt_vec + 255) / 256), 256>>>();
    transpose_x_kernel<<<dim3(HH, DD), 128>>>(x);
    repack_kernel<<<64, 256>>>(w);

    cudaFuncSetAttribute(conv_mma_kernel,
                         cudaFuncAttributeMaxDynamicSharedMemorySize, SMEM_TOTAL);
    dim3 grid(72, 31, 2);    // (24 h-tiles x 3 w-tiles), d, cout-groups
    conv_mma_kernel<<<grid, 256, SMEM_TOTAL>>>(gamma, beta, mean, var);

    const int scan_threads = 256;
    const int scan_blocks = (CIN * HW + scan_threads - 1) / scan_threads;
    sru_scan_kernel<<<scan_blocks, scan_threads>>>(out);
}

// round 15
// speedup vs baseline: 1.2424x; 1.0172x over previous
#include <cuda_runtime.h>
#include <cuda_fp16.h>
#include <cstdint>
#include <math.h>

#define CIN 64
#define COUT 256
#define DD 31
#define HH 96
#define WW 96
#define HW (HH*WW)
#define DHW (DD*HW)
#define EPS 1e-5f

#define BH 4
#define BW 32

// padded transposed x: [33][98] planes of [8 ci-chunk][104 w][16B]
#define XT_D 33
#define XT_H 98
#define XT_W 104
#define PLANE_BYTES (8*XT_W*16)          // 13312
__device__ __half g_xt[(size_t)XT_D * XT_H * PLANE_BYTES / 2];

__device__ __half g_gates[(size_t)COUT * DHW];   // activated gates [cout][d][h][w] fp16
// weights: [tap][2 coutgroup][8 ci-chunk][128 cout][8 ci] fp16 -> 16KB per (tap,group)
__device__ __half g_wth[27 * COUT * CIN];

// smem: A 2-stage ring of 16KB, then B [8 chunk][612 row][16B]
#define SMA_BYTES 16384
#define NSTAGE 2
#define SMB_OFF (NSTAGE*SMA_BYTES)               // 32768
#define B_ROWS 612                               // 3 dz * 6 he * 34 we
#define B_CHUNK_STRIDE (B_ROWS*16)               // 9792
#define SMEM_TOTAL (SMB_OFF + 8*B_CHUNK_STRIDE)  // 111104 (108.5 KB) -> 2 CTAs/SM

__device__ __forceinline__ uint32_t cvta_s(const void* p) {
    uint32_t a;
    asm("{ .reg .u64 t; cvta.to.shared.u64 t, %1; cvt.u32.u64 %0, t; }" : "=r"(a) : "l"(p));
    return a;
}
__device__ __forceinline__ float fast_tanh(float x) {
    float y; asm("tanh.approx.f32 %0, %1;" : "=f"(y) : "f"(x)); return y;
}
__device__ __forceinline__ void ldsm_x4(uint32_t& r0, uint32_t& r1, uint32_t& r2, uint32_t& r3,
                                        uint32_t addr) {
    asm volatile("ldmatrix.sync.aligned.m8n8.x4.shared.b16 {%0,%1,%2,%3}, [%4];"
        : "=r"(r0), "=r"(r1), "=r"(r2), "=r"(r3) : "r"(addr));
}
#define MBAR_INIT(mbar, count) \
    asm volatile("mbarrier.init.shared.b64 [%0], %1;" :: "r"((uint32_t)(mbar)), "r"((uint32_t)(count)) : "memory")
#define MBAR_EXPECT_TX(mbar, bytes) \
    asm volatile("mbarrier.arrive.expect_tx.shared.b64 _, [%0], %1;" \
        :: "r"((uint32_t)(mbar)), "r"((uint32_t)(bytes)) : "memory")
#define MBAR_ARRIVE(mbar) \
    asm volatile("mbarrier.arrive.shared.b64 _, [%0];" :: "r"((uint32_t)(mbar)) : "memory")
#define MBAR_WAIT(mbar, parity) do { \
    uint32_t _m = (uint32_t)(mbar); uint32_t _p = (uint32_t)(parity); uint32_t _done; \
    asm volatile("{\n\t.reg .pred p;\n\tmbarrier.try_wait.parity.acquire.cta.shared::cta.b64 p, [%1], %2;\n\tselp.b32 %0, 1, 0, p;\n\t}" \
        : "=r"(_done) : "r"(_m), "r"(_p) : "memory"); \
    if (!_done) { \
        asm volatile("{\n\t.reg .pred P1;\n\tWL_%=:\n\tmbarrier.try_wait.parity.acquire.cta.shared::cta.b64 P1, [%0], %1, 0x989680;\n\t@P1 bra.uni WD_%=;\n\tbra.uni WL_%=;\n\tWD_%=:\n\t}" \
            :: "r"(_m), "r"(_p) : "memory"); \
    } } while (0)
#define BULK_G2S(dst, src, bytes, mbar) \
    asm volatile("cp.async.bulk.shared::cluster.global.mbarrier::complete_tx::bytes [%0], [%1], %2, [%3];" \
        :: "r"((uint32_t)(dst)), "l"(src), "r"((uint32_t)(bytes)), "r"((uint32_t)(mbar)) : "memory")

// ---------------- pre-pass kernels ----------------
// Fused transpose + border zero:
// x[ci][d][h][w] f32 -> plane(dp,hp): [chunk][wp][16B] fp16; border rows zeroed.
__global__ void transpose_x_kernel(const float* __restrict__ x) {
    const int dp = blockIdx.y;       // 0..32
    const int hp = blockIdx.x;       // 0..97
    const int wp = threadIdx.x;      // 0..103
    if (wp >= XT_W) return;
    char* plane = (char*)g_xt + ((size_t)dp * XT_H + hp) * PLANE_BYTES;
    const bool interior = (dp >= 1) && (dp <= DD) && (hp >= 1) && (hp <= HH)
                        && (wp >= 1) && (wp <= WW);
    uint32_t pk[32];
    if (interior) {
        const float* src = x + (size_t)(dp - 1) * HW + (hp - 1) * WW + (wp - 1);
#pragma unroll
        for (int j = 0; j < 32; ++j) {
            float v0 = src[(size_t)(2 * j) * DHW];
            float v1 = src[(size_t)(2 * j + 1) * DHW];
            __half2 h2 = __float22half2_rn(make_float2(v0, v1));
            pk[j] = *reinterpret_cast<uint32_t*>(&h2);
        }
    } else {
#pragma unroll
        for (int j = 0; j < 32; ++j) pk[j] = 0u;
    }
#pragma unroll
    for (int c = 0; c < 8; ++c) {
        uint4 q = make_uint4(pk[c * 4], pk[c * 4 + 1], pk[c * 4 + 2], pk[c * 4 + 3]);
        *reinterpret_cast<uint4*>(plane + c * (XT_W * 16) + wp * 16) = q;
    }
}

// w[cout][cin][27] -> g_wth[tap][zg][chunk][cout_local 128][8 ci]
__global__ void repack_kernel(const float* __restrict__ w) {
    int id = blockIdx.x * blockDim.x + threadIdx.x;
    if (id >= COUT * CIN) return;
    int cout = id >> 6, cin = id & 63;
    const float* src = w + (size_t)id * 27;
    const int zg = cout >> 7, cl = cout & 127;
    const int chunk = cin >> 3, ci7 = cin & 7;
    const size_t base = ((size_t)zg * 8192) + chunk * 1024 + cl * 8 + ci7;
#pragma unroll
    for (int t = 0; t < 27; ++t)
        g_wth[(size_t)t * 16384 + base] = __float2half_rn(src[t]);
}

// ---------------- conv + BN + activation (unchanged from round 14) ----------------
__global__ __launch_bounds__(256, 2)
void conv_mma_kernel(const float* __restrict__ gamma, const float* __restrict__ beta,
                     const float* __restrict__ mean, const float* __restrict__ var)
{
    extern __shared__ __align__(128) char smem[];
    __shared__ __align__(8) uint64_t mbars[NSTAGE * 2 + 3];   // Ardy[2], Afree[2], B[3]
    const uint32_t smA_u = cvta_s(smem);
    const uint32_t smB_u = smA_u + SMB_OFF;
    uint32_t mbArdy[NSTAGE], mbAfree[NSTAGE], mbB[3];
#pragma unroll
    for (int i = 0; i < NSTAGE; ++i) { mbArdy[i] = cvta_s(&mbars[i]); mbAfree[i] = cvta_s(&mbars[NSTAGE + i]); }
#pragma unroll
    for (int i = 0; i < 3; ++i) mbB[i] = cvta_s(&mbars[2 * NSTAGE + i]);

    const int tid = threadIdx.x, wid = tid >> 5, lane = tid & 31;
    const int d = blockIdx.y;
    const int zg = blockIdx.z;
    const int coutBase = zg * 128;
    const int hBase = (blockIdx.x / 3) * BH, wBase = (blockIdx.x % 3) * BW;

    const char* wsrc = (const char*)g_wth + (size_t)zg * SMA_BYTES;

    // 8 warps: 4 along M (32 each), 2 along N (64 each)
    const int warpM = (wid >> 1) * 32, warpN = (wid & 1) * 64;
    const int mr = lane >> 2, nc = lane & 3;
    const int matsel = lane >> 3, rl = lane & 7;
    const int mhalf = matsel & 1, khalf = matsel >> 1;

    uint32_t aBase[2];
#pragma unroll
    for (int f = 0; f < 2; ++f)
        aBase[f] = smA_u + khalf * 2048 + (warpM + 16 * f + mhalf * 8 + rl) * 16;
    uint32_t bBase[4];
#pragma unroll
    for (int g2 = 0; g2 < 4; ++g2) {
        int n = warpN + g2 * 16 + mhalf * 8 + rl;
        bBase[g2] = smB_u + khalf * B_CHUNK_STRIDE + ((n >> 5) * 34 + (n & 31)) * 16;
    }

    if (tid == 0) {
#pragma unroll
        for (int i = 0; i < NSTAGE; ++i) { MBAR_INIT(mbArdy[i], 1); MBAR_INIT(mbAfree[i], 8); }
#pragma unroll
        for (int i = 0; i < 3; ++i) MBAR_INIT(mbB[i], 1);
    }
    __syncthreads();
    if (tid == 0) {
#pragma unroll
        for (int i = 0; i < 3; ++i) MBAR_EXPECT_TX(mbB[i], 48u * 544u);
    }
    __syncthreads();

    // ---- B: 144 copies of 544B, one per thread (dzl, he, chunk)
    if (tid < 144) {
        const int dzl = tid / 48, r2 = tid % 48;
        const int he = r2 / 8, chunk = r2 % 8;
        const char* src = (const char*)g_xt
            + ((size_t)(d + dzl) * XT_H + hBase + he) * PLANE_BYTES
            + chunk * (XT_W * 16) + wBase * 16;
        BULK_G2S(smB_u + chunk * B_CHUNK_STRIDE + (dzl * 204 + he * 34) * 16,
                 src, 544u, mbB[dzl]);
    }
    // ---- A taps 0..1
    if (tid == 0) {
#pragma unroll
        for (int t = 0; t < NSTAGE; ++t) {
            MBAR_EXPECT_TX(mbArdy[t], SMA_BYTES);
            BULK_G2S(smA_u + t * SMA_BYTES, wsrc + (size_t)t * 2 * SMA_BYTES,
                     SMA_BYTES, mbArdy[t]);
        }
    }

    float acc[2][8][4];
#pragma unroll
    for (int f = 0; f < 2; ++f)
#pragma unroll
        for (int g = 0; g < 8; ++g)
#pragma unroll
            for (int c = 0; c < 4; ++c) acc[f][g][c] = 0.0f;

    for (int tap = 0; tap < 27; ++tap) {
        const int kd = tap / 9, kh = (tap / 3) % 3, kw = tap % 3;
        if (kh == 0 && kw == 0) { MBAR_WAIT(mbB[kd], 0); }
        const int buf = tap % NSTAGE;
        MBAR_WAIT(mbArdy[buf], (tap / NSTAGE) & 1);

        const uint32_t aOff = (uint32_t)buf * SMA_BYTES;
        const uint32_t bOff = (uint32_t)(kd * 204 + kh * 34 + kw) * 16;
#pragma unroll
        for (int s = 0; s < 4; ++s) {
            uint32_t a[2][4];
#pragma unroll
            for (int f = 0; f < 2; ++f)
                ldsm_x4(a[f][0], a[f][1], a[f][2], a[f][3],
                        aBase[f] + aOff + s * 4096);
            uint32_t b[8][2];
#pragma unroll
            for (int g2 = 0; g2 < 4; ++g2)
                ldsm_x4(b[2 * g2][0], b[2 * g2 + 1][0],
                        b[2 * g2][1], b[2 * g2 + 1][1],
                        bBase[g2] + bOff + s * (2 * B_CHUNK_STRIDE));
#pragma unroll
            for (int f = 0; f < 2; ++f)
#pragma unroll
                for (int g = 0; g < 8; ++g) {
                    asm volatile(
                        "mma.sync.aligned.m16n8k16.row.col.f32.f16.f16.f32 "
                        "{%0,%1,%2,%3}, {%4,%5,%6,%7}, {%8,%9}, {%0,%1,%2,%3};"
                        : "+f"(acc[f][g][0]), "+f"(acc[f][g][1]),
                          "+f"(acc[f][g][2]), "+f"(acc[f][g][3])
                        : "r"(a[f][0]), "r"(a[f][1]), "r"(a[f][2]), "r"(a[f][3]),
                          "r"(b[g][0]), "r"(b[g][1]));
                }
        }
        if (lane == 0) MBAR_ARRIVE(mbAfree[buf]);
        if (tid == 0) {
            const int nt = tap + NSTAGE;
            if (nt < 27) {
                const int nb = nt % NSTAGE;
                MBAR_WAIT(mbAfree[nb], (nt / NSTAGE - 1) & 1);
                MBAR_EXPECT_TX(mbArdy[nb], SMA_BYTES);
                BULK_G2S(smA_u + nb * SMA_BYTES,
                         wsrc + (size_t)nt * 2 * SMA_BYTES, SMA_BYTES, mbArdy[nb]);
            }
        }
    }

    // ---- epilogue: BN + activation + STG (__half2)
#pragma unroll
    for (int f = 0; f < 2; ++f)
#pragma unroll
        for (int r = 0; r < 2; ++r) {
            const int cg = coutBase + warpM + 16 * f + 8 * r + mr;
            const float s = gamma[cg] * rsqrtf(var[cg] + EPS);
            const float sh = beta[cg] - mean[cg] * s;
            const int gt = cg >> 6;
            const bool sg = (gt == 1) || (gt == 2);
            __half* orow = g_gates + (size_t)cg * DHW + (size_t)d * HW;
#pragma unroll
            for (int g = 0; g < 8; ++g) {
                const int n0 = warpN + 8 * g + 2 * nc;
                const int h2 = n0 >> 5, w2 = n0 & 31;
                float v0 = acc[f][g][2 * r + 0] * s + sh;
                float v1 = acc[f][g][2 * r + 1] * s + sh;
                if (sg) {
                    v0 = 0.5f * fast_tanh(0.5f * v0) + 0.5f;
                    v1 = 0.5f * fast_tanh(0.5f * v1) + 0.5f;
                } else {
                    v0 = fast_tanh(v0);
                    v1 = fast_tanh(v1);
                }
                *reinterpret_cast<__half2*>(orow + (hBase + h2) * WW + wBase + w2)
                    = __float22half2_rn(make_float2(v0, v1));
            }
        }
}

// ---------------- SRU scan over depth (vectorized 4-wide) ----------------
__global__ void sru_scan_kernel(float* __restrict__ out)
{
    const int idx = blockIdx.x * blockDim.x + threadIdx.x;
    if (idx >= CIN * (HW / 4)) return;
    const int c = idx / (HW / 4);
    const int hw4 = (idx % (HW / 4)) * 4;

    const __half* pw = g_gates + (size_t)(0 * 64 + c) * DHW + hw4;
    const __half* pf = g_gates + (size_t)(1 * 64 + c) * DHW + hw4;
    const __half* pr = g_gates + (size_t)(2 * 64 + c) * DHW + hw4;
    const __half* px = g_gates + (size_t)(3 * 64 + c) * DHW + hw4;
    float* po = out + (size_t)c * DHW + hw4;

    float C[4];
    {
        const __half2* f2 = (const __half2*)pf;
        const __half2* r2 = (const __half2*)pr;
        const __half2* x2 = (const __half2*)px;
        float4 ov;
        float2 fa = __half22float2(f2[0]), fb = __half22float2(f2[1]);
        float2 ra = __half22float2(r2[0]), rb = __half22float2(r2[1]);
        float2 xa = __half22float2(x2[0]), xb = __half22float2(x2[1]);
        C[0] = 1.0f - fa.x; C[1] = 1.0f - fa.y; C[2] = 1.0f - fb.x; C[3] = 1.0f - fb.y;
        ov.x = ra.x * C[0] + (1.0f - ra.x) * xa.x;
        ov.y = ra.y * C[1] + (1.0f - ra.y) * xa.y;
        ov.z = rb.x * C[2] + (1.0f - rb.x) * xb.x;
        ov.w = rb.y * C[3] + (1.0f - rb.y) * xb.y;
        *reinterpret_cast<float4*>(po) = ov;
    }

    for (int dd = 1; dd < DD; ++dd) {
        const int off = dd * HW;
        const __half2* w2 = (const __half2*)(pw + off);
        const __half2* f2 = (const __half2*)(pf + off);
        const __half2* r2 = (const __half2*)(pr + off);
        const __half2* x2 = (const __half2*)(px + off);
        float2 wa = __half22float2(w2[0]), wb = __half22float2(w2[1]);
        float2 fa = __half22float2(f2[0]), fb = __half22float2(f2[1]);
        float2 ra = __half22float2(r2[0]), rb = __half22float2(r2[1]);
        float2 xa = __half22float2(x2[0]), xb = __half22float2(x2[1]);
        C[0] = fa.x * C[0] + (1.0f - fa.x) * wa.x;
        C[1] = fa.y * C[1] + (1.0f - fa.y) * wa.y;
        C[2] = fb.x * C[2] + (1.0f - fb.x) * wb.x;
        C[3] = fb.y * C[3] + (1.0f - fb.y) * wb.y;
        float4 ov;
        ov.x = ra.x * C[0] + (1.0f - ra.x) * xa.x;
        ov.y = ra.y * C[1] + (1.0f - ra.y) * xa.y;
        ov.z = rb.x * C[2] + (1.0f - rb.x) * xb.x;
        ov.w = rb.y * C[3] + (1.0f - rb.y) * xb.y;
        *reinterpret_cast<float4*>(po + off) = ov;
    }
}

extern "C" void kernel_launch(void* const* d_in, const int* in_sizes, int n_in,
                              void* d_out, int out_size)
{
    const float* x     = (const float*)d_in[0];
    const float* w     = (const float*)d_in[1];
    const float* gamma = (const float*)d_in[2];
    const float* beta  = (const float*)d_in[3];
    const float* mean  = (const float*)d_in[4];
    const float* var   = (const float*)d_in[5];
    float* out = (float*)d_out;

    transpose_x_kernel<<<dim3(XT_H, XT_D), XT_W>>>(x);
    repack_kernel<<<64, 256>>>(w);

    cudaFuncSetAttribute(conv_mma_kernel,
                         cudaFuncAttributeMaxDynamicSharedMemorySize, SMEM_TOTAL);
    dim3 grid(72, 31, 2);    // (24 h-tiles x 3 w-tiles), d, cout-groups
    conv_mma_kernel<<<grid, 256, SMEM_TOTAL>>>(gamma, beta, mean, var);

    const int scan_threads = 256;
    const int scan_total = CIN * (HW / 4);
    const int scan_blocks = (scan_total + scan_threads - 1) / scan_threads;
    sru_scan_kernel<<<scan_blocks, scan_threads>>>(out);
}

// round 16
// speedup vs baseline: 1.4068x; 1.1323x over previous
#include <cuda_runtime.h>
#include <cuda_fp16.h>
#include <cstdint>
#include <math.h>

#define CIN 64
#define COUT 256
#define DD 31
#define HH 96
#define WW 96
#define HW (HH*WW)
#define DHW (DD*HW)
#define EPS 1e-5f

#define BH 4
#define BW 32

// padded transposed x: [33][98] planes of [8 ci-chunk][104 w][16B]
#define XT_D 33
#define XT_H 98
#define XT_W 104
#define PLANE_BYTES (8*XT_W*16)          // 13312
__device__ __half g_xt[(size_t)XT_D * XT_H * PLANE_BYTES / 2];

__device__ __half g_gates[(size_t)COUT * DHW];   // activated gates [cout][d][h][w] fp16
// weights: [tap][2 coutgroup][8 ci-chunk][128 cout][8 ci] fp16 -> 16KB per (tap,group)
__device__ __half g_wth[27 * COUT * CIN];

// smem: A 2-stage ring of 16KB, then B [8 chunk][612 row][16B]
#define SMA_BYTES 16384
#define NSTAGE 2
#define SMB_OFF (NSTAGE*SMA_BYTES)               // 32768
#define B_ROWS 612                               // 3 dz * 6 he * 34 we
#define B_CHUNK_STRIDE (B_ROWS*16)               // 9792
#define SMEM_TOTAL (SMB_OFF + 8*B_CHUNK_STRIDE)  // 111104 (108.5 KB) -> 2 CTAs/SM

__device__ __forceinline__ uint32_t cvta_s(const void* p) {
    uint32_t a;
    asm("{ .reg .u64 t; cvta.to.shared.u64 t, %1; cvt.u32.u64 %0, t; }" : "=r"(a) : "l"(p));
    return a;
}
__device__ __forceinline__ float fast_tanh(float x) {
    float y; asm("tanh.approx.f32 %0, %1;" : "=f"(y) : "f"(x)); return y;
}
__device__ __forceinline__ void ldsm_x4(uint32_t& r0, uint32_t& r1, uint32_t& r2, uint32_t& r3,
                                        uint32_t addr) {
    asm volatile("ldmatrix.sync.aligned.m8n8.x4.shared.b16 {%0,%1,%2,%3}, [%4];"
        : "=r"(r0), "=r"(r1), "=r"(r2), "=r"(r3) : "r"(addr));
}
#define MBAR_INIT(mbar, count) \
    asm volatile("mbarrier.init.shared.b64 [%0], %1;" :: "r"((uint32_t)(mbar)), "r"((uint32_t)(count)) : "memory")
#define MBAR_EXPECT_TX(mbar, bytes) \
    asm volatile("mbarrier.arrive.expect_tx.shared.b64 _, [%0], %1;" \
        :: "r"((uint32_t)(mbar)), "r"((uint32_t)(bytes)) : "memory")
#define MBAR_ARRIVE(mbar) \
    asm volatile("mbarrier.arrive.shared.b64 _, [%0];" :: "r"((uint32_t)(mbar)) : "memory")
#define MBAR_WAIT(mbar, parity) do { \
    uint32_t _m = (uint32_t)(mbar); uint32_t _p = (uint32_t)(parity); uint32_t _done; \
    asm volatile("{\n\t.reg .pred p;\n\tmbarrier.try_wait.parity.acquire.cta.shared::cta.b64 p, [%1], %2;\n\tselp.b32 %0, 1, 0, p;\n\t}" \
        : "=r"(_done) : "r"(_m), "r"(_p) : "memory"); \
    if (!_done) { \
        asm volatile("{\n\t.reg .pred P1;\n\tWL_%=:\n\tmbarrier.try_wait.parity.acquire.cta.shared::cta.b64 P1, [%0], %1, 0x989680;\n\t@P1 bra.uni WD_%=;\n\tbra.uni WL_%=;\n\tWD_%=:\n\t}" \
            :: "r"(_m), "r"(_p) : "memory"); \
    } } while (0)
#define BULK_G2S(dst, src, bytes, mbar) \
    asm volatile("cp.async.bulk.shared::cluster.global.mbarrier::complete_tx::bytes [%0], [%1], %2, [%3];" \
        :: "r"((uint32_t)(dst)), "l"(src), "r"((uint32_t)(bytes)), "r"((uint32_t)(mbar)) : "memory")

// ---------------- pre-pass kernels ----------------
// Fused transpose + border zero
__global__ void transpose_x_kernel(const float* __restrict__ x) {
    const int dp = blockIdx.y;       // 0..32
    const int hp = blockIdx.x;       // 0..97
    const int wp = threadIdx.x;      // 0..103
    if (wp >= XT_W) return;
    char* plane = (char*)g_xt + ((size_t)dp * XT_H + hp) * PLANE_BYTES;
    const bool interior = (dp >= 1) && (dp <= DD) && (hp >= 1) && (hp <= HH)
                        && (wp >= 1) && (wp <= WW);
    uint32_t pk[32];
    if (interior) {
        const float* src = x + (size_t)(dp - 1) * HW + (hp - 1) * WW + (wp - 1);
#pragma unroll
        for (int j = 0; j < 32; ++j) {
            float v0 = src[(size_t)(2 * j) * DHW];
            float v1 = src[(size_t)(2 * j + 1) * DHW];
            __half2 h2 = __float22half2_rn(make_float2(v0, v1));
            pk[j] = *reinterpret_cast<uint32_t*>(&h2);
        }
    } else {
#pragma unroll
        for (int j = 0; j < 32; ++j) pk[j] = 0u;
    }
#pragma unroll
    for (int c = 0; c < 8; ++c) {
        uint4 q = make_uint4(pk[c * 4], pk[c * 4 + 1], pk[c * 4 + 2], pk[c * 4 + 3]);
        *reinterpret_cast<uint4*>(plane + c * (XT_W * 16) + wp * 16) = q;
    }
}

// w[cout][cin][27] -> g_wth[tap][zg][chunk][cout_local 128][8 ci]
__global__ void repack_kernel(const float* __restrict__ w) {
    int id = blockIdx.x * blockDim.x + threadIdx.x;
    if (id >= COUT * CIN) return;
    int cout = id >> 6, cin = id & 63;
    const float* src = w + (size_t)id * 27;
    const int zg = cout >> 7, cl = cout & 127;
    const int chunk = cin >> 3, ci7 = cin & 7;
    const size_t base = ((size_t)zg * 8192) + chunk * 1024 + cl * 8 + ci7;
#pragma unroll
    for (int t = 0; t < 27; ++t)
        g_wth[(size_t)t * 16384 + base] = __float2half_rn(src[t]);
}

// ---------------- conv + BN + activation ----------------
__global__ __launch_bounds__(256, 2)
void conv_mma_kernel(const float* __restrict__ gamma, const float* __restrict__ beta,
                     const float* __restrict__ mean, const float* __restrict__ var)
{
    extern __shared__ __align__(128) char smem[];
    __shared__ __align__(8) uint64_t mbars[NSTAGE * 2 + 3];   // Ardy[2], Afree[2], B[3]
    const uint32_t smA_u = cvta_s(smem);
    const uint32_t smB_u = smA_u + SMB_OFF;
    uint32_t mbArdy[NSTAGE], mbAfree[NSTAGE], mbB[3];
#pragma unroll
    for (int i = 0; i < NSTAGE; ++i) { mbArdy[i] = cvta_s(&mbars[i]); mbAfree[i] = cvta_s(&mbars[NSTAGE + i]); }
#pragma unroll
    for (int i = 0; i < 3; ++i) mbB[i] = cvta_s(&mbars[2 * NSTAGE + i]);

    const int tid = threadIdx.x, wid = tid >> 5, lane = tid & 31;
    const int d = blockIdx.y;
    const int zg = blockIdx.z;
    const int coutBase = zg * 128;
    const int hBase = (blockIdx.x / 3) * BH, wBase = (blockIdx.x % 3) * BW;

    const char* wsrc = (const char*)g_wth + (size_t)zg * SMA_BYTES;

    // 8 warps: 4 along M (32 each), 2 along N (64 each)
    const int warpM = (wid >> 1) * 32, warpN = (wid & 1) * 64;
    const int mr = lane >> 2, nc = lane & 3;
    const int matsel = lane >> 3, rl = lane & 7;
    const int mhalf = matsel & 1, khalf = matsel >> 1;

    uint32_t aBase[2];
#pragma unroll
    for (int f = 0; f < 2; ++f)
        aBase[f] = smA_u + khalf * 2048 + (warpM + 16 * f + mhalf * 8 + rl) * 16;
    uint32_t bBase[4];
#pragma unroll
    for (int g2 = 0; g2 < 4; ++g2) {
        int n = warpN + g2 * 16 + mhalf * 8 + rl;
        bBase[g2] = smB_u + khalf * B_CHUNK_STRIDE + ((n >> 5) * 34 + (n & 31)) * 16;
    }

    if (tid == 0) {
#pragma unroll
        for (int i = 0; i < NSTAGE; ++i) { MBAR_INIT(mbArdy[i], 1); MBAR_INIT(mbAfree[i], 8); }
#pragma unroll
        for (int i = 0; i < 3; ++i) MBAR_INIT(mbB[i], 1);
    }
    __syncthreads();
    if (tid == 0) {
#pragma unroll
        for (int i = 0; i < 3; ++i) MBAR_EXPECT_TX(mbB[i], 48u * 544u);
    }
    __syncthreads();

    // ---- B: 144 copies of 544B, one per thread (dzl, he, chunk)
    if (tid < 144) {
        const int dzl = tid / 48, r2 = tid % 48;
        const int he = r2 / 8, chunk = r2 % 8;
        const char* src = (const char*)g_xt
            + ((size_t)(d + dzl) * XT_H + hBase + he) * PLANE_BYTES
            + chunk * (XT_W * 16) + wBase * 16;
        BULK_G2S(smB_u + chunk * B_CHUNK_STRIDE + (dzl * 204 + he * 34) * 16,
                 src, 544u, mbB[dzl]);
    }
    // ---- A taps 0..1
    if (tid == 0) {
#pragma unroll
        for (int t = 0; t < NSTAGE; ++t) {
            MBAR_EXPECT_TX(mbArdy[t], SMA_BYTES);
            BULK_G2S(smA_u + t * SMA_BYTES, wsrc + (size_t)t * 2 * SMA_BYTES,
                     SMA_BYTES, mbArdy[t]);
        }
    }

    float acc[2][8][4];
#pragma unroll
    for (int f = 0; f < 2; ++f)
#pragma unroll
        for (int g = 0; g < 8; ++g)
#pragma unroll
            for (int c = 0; c < 4; ++c) acc[f][g][c] = 0.0f;

#pragma unroll
    for (int tap = 0; tap < 27; ++tap) {
        const int kd = tap / 9, kh = (tap / 3) % 3, kw = tap % 3;
        if (kh == 0 && kw == 0) { MBAR_WAIT(mbB[kd], 0); }
        const int buf = tap % NSTAGE;
        MBAR_WAIT(mbArdy[buf], (tap / NSTAGE) & 1);

        const uint32_t aOff = (uint32_t)buf * SMA_BYTES;
        const uint32_t bOff = (uint32_t)(kd * 204 + kh * 34 + kw) * 16;
#pragma unroll
        for (int s = 0; s < 4; ++s) {
            uint32_t a[2][4];
#pragma unroll
            for (int f = 0; f < 2; ++f)
                ldsm_x4(a[f][0], a[f][1], a[f][2], a[f][3],
                        aBase[f] + aOff + s * 4096);
            uint32_t b[8][2];
#pragma unroll
            for (int g2 = 0; g2 < 4; ++g2)
                ldsm_x4(b[2 * g2][0], b[2 * g2 + 1][0],
                        b[2 * g2][1], b[2 * g2 + 1][1],
                        bBase[g2] + bOff + s * (2 * B_CHUNK_STRIDE));
#pragma unroll
            for (int f = 0; f < 2; ++f)
#pragma unroll
                for (int g = 0; g < 8; ++g) {
                    asm volatile(
                        "mma.sync.aligned.m16n8k16.row.col.f32.f16.f16.f32 "
                        "{%0,%1,%2,%3}, {%4,%5,%6,%7}, {%8,%9}, {%0,%1,%2,%3};"
                        : "+f"(acc[f][g][0]), "+f"(acc[f][g][1]),
                          "+f"(acc[f][g][2]), "+f"(acc[f][g][3])
                        : "r"(a[f][0]), "r"(a[f][1]), "r"(a[f][2]), "r"(a[f][3]),
                          "r"(b[g][0]), "r"(b[g][1]));
                }
        }
        if (lane == 0) MBAR_ARRIVE(mbAfree[buf]);
        if (tid == 0) {
            const int nt = tap + NSTAGE;
            if (nt < 27) {
                const int nb = nt % NSTAGE;
                MBAR_WAIT(mbAfree[nb], (nt / NSTAGE - 1) & 1);
                MBAR_EXPECT_TX(mbArdy[nb], SMA_BYTES);
                BULK_G2S(smA_u + nb * SMA_BYTES,
                         wsrc + (size_t)nt * 2 * SMA_BYTES, SMA_BYTES, mbArdy[nb]);
            }
        }
    }

    // ---- epilogue: BN + activation + STG (__half2)
#pragma unroll
    for (int f = 0; f < 2; ++f)
#pragma unroll
        for (int r = 0; r < 2; ++r) {
            const int cg = coutBase + warpM + 16 * f + 8 * r + mr;
            const float s = gamma[cg] * rsqrtf(var[cg] + EPS);
            const float sh = beta[cg] - mean[cg] * s;
            const int gt = cg >> 6;
            const bool sg = (gt == 1) || (gt == 2);
            __half* orow = g_gates + (size_t)cg * DHW + (size_t)d * HW;
#pragma unroll
            for (int g = 0; g < 8; ++g) {
                const int n0 = warpN + 8 * g + 2 * nc;
                const int h2 = n0 >> 5, w2 = n0 & 31;
                float v0 = acc[f][g][2 * r + 0] * s + sh;
                float v1 = acc[f][g][2 * r + 1] * s + sh;
                if (sg) {
                    v0 = 0.5f * fast_tanh(0.5f * v0) + 0.5f;
                    v1 = 0.5f * fast_tanh(0.5f * v1) + 0.5f;
                } else {
                    v0 = fast_tanh(v0);
                    v1 = fast_tanh(v1);
                }
                *reinterpret_cast<__half2*>(orow + (hBase + h2) * WW + wBase + w2)
                    = __float22half2_rn(make_float2(v0, v1));
            }
        }
}

// ---------------- SRU scan over depth (vectorized 8-wide) ----------------
__global__ void sru_scan_kernel(float* __restrict__ out)
{
    const int idx = blockIdx.x * blockDim.x + threadIdx.x;
    if (idx >= CIN * (HW / 8)) return;
    const int c = idx / (HW / 8);
    const int hw8 = (idx % (HW / 8)) * 8;

    const __half* pw = g_gates + (size_t)(0 * 64 + c) * DHW + hw8;
    const __half* pf = g_gates + (size_t)(1 * 64 + c) * DHW + hw8;
    const __half* pr = g_gates + (size_t)(2 * 64 + c) * DHW + hw8;
    const __half* px = g_gates + (size_t)(3 * 64 + c) * DHW + hw8;
    float* po = out + (size_t)c * DHW + hw8;

    float C[8];
    {
        uint4 fq = *reinterpret_cast<const uint4*>(pf);
        uint4 rq = *reinterpret_cast<const uint4*>(pr);
        uint4 xq = *reinterpret_cast<const uint4*>(px);
        const __half2* f2 = (const __half2*)&fq;
        const __half2* r2 = (const __half2*)&rq;
        const __half2* x2 = (const __half2*)&xq;
        float ov[8];
#pragma unroll
        for (int q = 0; q < 4; ++q) {
            float2 fa = __half22float2(f2[q]);
            float2 ra = __half22float2(r2[q]);
            float2 xa = __half22float2(x2[q]);
            C[2 * q]     = 1.0f - fa.x;
            C[2 * q + 1] = 1.0f - fa.y;
            ov[2 * q]     = ra.x * C[2 * q]     + (1.0f - ra.x) * xa.x;
            ov[2 * q + 1] = ra.y * C[2 * q + 1] + (1.0f - ra.y) * xa.y;
        }
        reinterpret_cast<float4*>(po)[0] = make_float4(ov[0], ov[1], ov[2], ov[3]);
        reinterpret_cast<float4*>(po)[1] = make_float4(ov[4], ov[5], ov[6], ov[7]);
    }

    for (int dd = 1; dd < DD; ++dd) {
        const int off = dd * HW;
        uint4 wq = *reinterpret_cast<const uint4*>(pw + off);
        uint4 fq = *reinterpret_cast<const uint4*>(pf + off);
        uint4 rq = *reinterpret_cast<const uint4*>(pr + off);
        uint4 xq = *reinterpret_cast<const uint4*>(px + off);
        const __half2* w2 = (const __half2*)&wq;
        const __half2* f2 = (const __half2*)&fq;
        const __half2* r2 = (const __half2*)&rq;
        const __half2* x2 = (const __half2*)&xq;
        float ov[8];
#pragma unroll
        for (int q = 0; q < 4; ++q) {
            float2 wa = __half22float2(w2[q]);
            float2 fa = __half22float2(f2[q]);
            float2 ra = __half22float2(r2[q]);
            float2 xa = __half22float2(x2[q]);
            C[2 * q]     = fa.x * C[2 * q]     + (1.0f - fa.x) * wa.x;
            C[2 * q + 1] = fa.y * C[2 * q + 1] + (1.0f - fa.y) * wa.y;
            ov[2 * q]     = ra.x * C[2 * q]     + (1.0f - ra.x) * xa.x;
            ov[2 * q + 1] = ra.y * C[2 * q + 1] + (1.0f - ra.y) * xa.y;
        }
        reinterpret_cast<float4*>(po + off)[0] = make_float4(ov[0], ov[1], ov[2], ov[3]);
        reinterpret_cast<float4*>(po + off)[1] = make_float4(ov[4], ov[5], ov[6], ov[7]);
    }
}

extern "C" void kernel_launch(void* const* d_in, const int* in_sizes, int n_in,
                              void* d_out, int out_size)
{
    const float* x     = (const float*)d_in[0];
    const float* w     = (const float*)d_in[1];
    const float* gamma = (const float*)d_in[2];
    const float* beta  = (const float*)d_in[3];
    const float* mean  = (const float*)d_in[4];
    const float* var   = (const float*)d_in[5];
    float* out = (float*)d_out;

    transpose_x_kernel<<<dim3(XT_H, XT_D), XT_W>>>(x);
    repack_kernel<<<64, 256>>>(w);

    cudaFuncSetAttribute(conv_mma_kernel,
                         cudaFuncAttributeMaxDynamicSharedMemorySize, SMEM_TOTAL);
    dim3 grid(72, 31, 2);    // (24 h-tiles x 3 w-tiles), d, cout-groups
    conv_mma_kernel<<<grid, 256, SMEM_TOTAL>>>(gamma, beta, mean, var);

    const int scan_threads = 256;
    const int scan_total = CIN * (HW / 8);
    const int scan_blocks = (scan_total + scan_threads - 1) / scan_threads;
    sru_scan_kernel<<<scan_blocks, scan_threads>>>(out);
}

// round 17
// speedup vs baseline: 1.4196x; 1.0091x over previous
#include <cuda_runtime.h>
#include <cuda_fp16.h>
#include <cstdint>
#include <math.h>

#define CIN 64
#define COUT 256
#define DD 31
#define HH 96
#define WW 96
#define HW (HH*WW)
#define DHW (DD*HW)
#define EPS 1e-5f

#define BH 4
#define BW 32

// padded transposed x: [33][98] planes of [8 ci-chunk][104 w][16B]
#define XT_D 33
#define XT_H 98
#define XT_W 104
#define PLANE_BYTES (8*XT_W*16)          // 13312
__device__ __half g_xt[(size_t)XT_D * XT_H * PLANE_BYTES / 2];

__device__ __half g_gates[(size_t)COUT * DHW];   // activated gates [cout][d][h][w] fp16
// weights: [tap][2 coutgroup][8 ci-chunk][128 cout][8 ci] fp16 -> 16KB per (tap,group)
__device__ __half g_wth[27 * COUT * CIN];

// smem: A 2-stage ring of 16KB, then B [8 chunk][612 row][16B]
#define SMA_BYTES 16384
#define NSTAGE 2
#define SMB_OFF (NSTAGE*SMA_BYTES)               // 32768
#define B_ROWS 612                               // 3 dz * 6 he * 34 we
#define B_CHUNK_STRIDE (B_ROWS*16)               // 9792
#define SMEM_TOTAL (SMB_OFF + 8*B_CHUNK_STRIDE)  // 111104 (108.5 KB) -> 2 CTAs/SM

__device__ __forceinline__ uint32_t cvta_s(const void* p) {
    uint32_t a;
    asm("{ .reg .u64 t; cvta.to.shared.u64 t, %1; cvt.u32.u64 %0, t; }" : "=r"(a) : "l"(p));
    return a;
}
__device__ __forceinline__ float fast_tanh(float x) {
    float y; asm("tanh.approx.f32 %0, %1;" : "=f"(y) : "f"(x)); return y;
}
__device__ __forceinline__ void ldsm_x4(uint32_t& r0, uint32_t& r1, uint32_t& r2, uint32_t& r3,
                                        uint32_t addr) {
    asm volatile("ldmatrix.sync.aligned.m8n8.x4.shared.b16 {%0,%1,%2,%3}, [%4];"
        : "=r"(r0), "=r"(r1), "=r"(r2), "=r"(r3) : "r"(addr));
}
#define MBAR_INIT(mbar, count) \
    asm volatile("mbarrier.init.shared.b64 [%0], %1;" :: "r"((uint32_t)(mbar)), "r"((uint32_t)(count)) : "memory")
#define MBAR_EXPECT_TX(mbar, bytes) \
    asm volatile("mbarrier.arrive.expect_tx.shared.b64 _, [%0], %1;" \
        :: "r"((uint32_t)(mbar)), "r"((uint32_t)(bytes)) : "memory")
#define MBAR_ARRIVE(mbar) \
    asm volatile("mbarrier.arrive.shared.b64 _, [%0];" :: "r"((uint32_t)(mbar)) : "memory")
#define MBAR_WAIT(mbar, parity) do { \
    uint32_t _m = (uint32_t)(mbar); uint32_t _p = (uint32_t)(parity); uint32_t _done; \
    asm volatile("{\n\t.reg .pred p;\n\tmbarrier.try_wait.parity.acquire.cta.shared::cta.b64 p, [%1], %2;\n\tselp.b32 %0, 1, 0, p;\n\t}" \
        : "=r"(_done) : "r"(_m), "r"(_p) : "memory"); \
    if (!_done) { \
        asm volatile("{\n\t.reg .pred P1;\n\tWL_%=:\n\tmbarrier.try_wait.parity.acquire.cta.shared::cta.b64 P1, [%0], %1, 0x989680;\n\t@P1 bra.uni WD_%=;\n\tbra.uni WL_%=;\n\tWD_%=:\n\t}" \
            :: "r"(_m), "r"(_p) : "memory"); \
    } } while (0)
#define BULK_G2S(dst, src, bytes, mbar) \
    asm volatile("cp.async.bulk.shared::cluster.global.mbarrier::complete_tx::bytes [%0], [%1], %2, [%3];" \
        :: "r"((uint32_t)(dst)), "l"(src), "r"((uint32_t)(bytes)), "r"((uint32_t)(mbar)) : "memory")

// ---------------- fused pre-pass: transpose+pad (rows 0..XT_D-1) | repack (row XT_D) ----------------
__global__ void prepass_kernel(const float* __restrict__ x, const float* __restrict__ w) {
    if (blockIdx.y == XT_D) {
        // weight repack: w[cout][cin][27] -> g_wth[tap][zg][chunk][cout_local 128][8 ci]
        for (int id = blockIdx.x * blockDim.x + threadIdx.x; id < COUT * CIN;
             id += XT_H * XT_W) {
            const int cout = id >> 6, cin = id & 63;
            const float* src = w + (size_t)id * 27;
            const int zg = cout >> 7, cl = cout & 127;
            const int chunk = cin >> 3, ci7 = cin & 7;
            const size_t base = ((size_t)zg * 8192) + chunk * 1024 + cl * 8 + ci7;
#pragma unroll
            for (int t = 0; t < 27; ++t)
                g_wth[(size_t)t * 16384 + base] = __float2half_rn(src[t]);
        }
        return;
    }
    const int dp = blockIdx.y;       // 0..32
    const int hp = blockIdx.x;       // 0..97
    const int wp = threadIdx.x;      // 0..103
    if (wp >= XT_W) return;
    char* plane = (char*)g_xt + ((size_t)dp * XT_H + hp) * PLANE_BYTES;
    const bool interior = (dp >= 1) && (dp <= DD) && (hp >= 1) && (hp <= HH)
                        && (wp >= 1) && (wp <= WW);
    uint32_t pk[32];
    if (interior) {
        const float* src = x + (size_t)(dp - 1) * HW + (hp - 1) * WW + (wp - 1);
#pragma unroll
        for (int j = 0; j < 32; ++j) {
            float v0 = src[(size_t)(2 * j) * DHW];
            float v1 = src[(size_t)(2 * j + 1) * DHW];
            __half2 h2 = __float22half2_rn(make_float2(v0, v1));
            pk[j] = *reinterpret_cast<uint32_t*>(&h2);
        }
    } else {
#pragma unroll
        for (int j = 0; j < 32; ++j) pk[j] = 0u;
    }
#pragma unroll
    for (int c = 0; c < 8; ++c) {
        uint4 q = make_uint4(pk[c * 4], pk[c * 4 + 1], pk[c * 4 + 2], pk[c * 4 + 3]);
        *reinterpret_cast<uint4*>(plane + c * (XT_W * 16) + wp * 16) = q;
    }
}

// ---------------- conv + BN + activation ----------------
__global__ __launch_bounds__(256, 2)
void conv_mma_kernel(const float* __restrict__ gamma, const float* __restrict__ beta,
                     const float* __restrict__ mean, const float* __restrict__ var)
{
    extern __shared__ __align__(128) char smem[];
    __shared__ __align__(8) uint64_t mbars[NSTAGE * 2 + 3];   // Ardy[2], Afree[2], B[3]
    const uint32_t smA_u = cvta_s(smem);
    const uint32_t smB_u = smA_u + SMB_OFF;
    uint32_t mbArdy[NSTAGE], mbAfree[NSTAGE], mbB[3];
#pragma unroll
    for (int i = 0; i < NSTAGE; ++i) { mbArdy[i] = cvta_s(&mbars[i]); mbAfree[i] = cvta_s(&mbars[NSTAGE + i]); }
#pragma unroll
    for (int i = 0; i < 3; ++i) mbB[i] = cvta_s(&mbars[2 * NSTAGE + i]);

    const int tid = threadIdx.x, wid = tid >> 5, lane = tid & 31;
    const int d = blockIdx.y;
    const int zg = blockIdx.z;
    const int coutBase = zg * 128;
    const int hBase = (blockIdx.x / 3) * BH, wBase = (blockIdx.x % 3) * BW;

    const char* wsrc = (const char*)g_wth + (size_t)zg * SMA_BYTES;

    // border-zero tap skip: kd=0 plane zero at d=0; kd=2 plane zero at d=30
    const bool skip_kd0 = (d == 0);
    const bool skip_kd2 = (d == DD - 1);

    // 8 warps: 4 along M (32 each), 2 along N (64 each)
    const int warpM = (wid >> 1) * 32, warpN = (wid & 1) * 64;
    const int mr = lane >> 2, nc = lane & 3;
    const int matsel = lane >> 3, rl = lane & 7;
    const int mhalf = matsel & 1, khalf = matsel >> 1;

    uint32_t aBase[2];
#pragma unroll
    for (int f = 0; f < 2; ++f)
        aBase[f] = smA_u + khalf * 2048 + (warpM + 16 * f + mhalf * 8 + rl) * 16;
    uint32_t bBase[4];
#pragma unroll
    for (int g2 = 0; g2 < 4; ++g2) {
        int n = warpN + g2 * 16 + mhalf * 8 + rl;
        bBase[g2] = smB_u + khalf * B_CHUNK_STRIDE + ((n >> 5) * 34 + (n & 31)) * 16;
    }

    if (tid == 0) {
#pragma unroll
        for (int i = 0; i < NSTAGE; ++i) { MBAR_INIT(mbArdy[i], 1); MBAR_INIT(mbAfree[i], 8); }
#pragma unroll
        for (int i = 0; i < 3; ++i) MBAR_INIT(mbB[i], 1);
    }
    __syncthreads();
    if (tid == 0) {
#pragma unroll
        for (int i = 0; i < 3; ++i) MBAR_EXPECT_TX(mbB[i], 48u * 544u);
    }
    __syncthreads();

    // ---- B: 144 copies of 544B, one per thread (dzl, he, chunk)
    if (tid < 144) {
        const int dzl = tid / 48, r2 = tid % 48;
        const int he = r2 / 8, chunk = r2 % 8;
        const char* src = (const char*)g_xt
            + ((size_t)(d + dzl) * XT_H + hBase + he) * PLANE_BYTES
            + chunk * (XT_W * 16) + wBase * 16;
        BULK_G2S(smB_u + chunk * B_CHUNK_STRIDE + (dzl * 204 + he * 34) * 16,
                 src, 544u, mbB[dzl]);
    }
    // ---- A taps 0..1
    if (tid == 0) {
#pragma unroll
        for (int t = 0; t < NSTAGE; ++t) {
            MBAR_EXPECT_TX(mbArdy[t], SMA_BYTES);
            BULK_G2S(smA_u + t * SMA_BYTES, wsrc + (size_t)t * 2 * SMA_BYTES,
                     SMA_BYTES, mbArdy[t]);
        }
    }

    float acc[2][8][4];
#pragma unroll
    for (int f = 0; f < 2; ++f)
#pragma unroll
        for (int g = 0; g < 8; ++g)
#pragma unroll
            for (int c = 0; c < 4; ++c) acc[f][g][c] = 0.0f;

#pragma unroll
    for (int tap = 0; tap < 27; ++tap) {
        const int kd = tap / 9, kh = (tap / 3) % 3, kw = tap % 3;
        if (kh == 0 && kw == 0) { MBAR_WAIT(mbB[kd], 0); }
        const int buf = tap % NSTAGE;
        MBAR_WAIT(mbArdy[buf], (tap / NSTAGE) & 1);

        const bool skip = (kd == 0) ? skip_kd0 : ((kd == 2) ? skip_kd2 : false);
        if (!skip) {
            const uint32_t aOff = (uint32_t)buf * SMA_BYTES;
            const uint32_t bOff = (uint32_t)(kd * 204 + kh * 34 + kw) * 16;
#pragma unroll
            for (int s = 0; s < 4; ++s) {
                uint32_t a[2][4];
#pragma unroll
                for (int f = 0; f < 2; ++f)
                    ldsm_x4(a[f][0], a[f][1], a[f][2], a[f][3],
                            aBase[f] + aOff + s * 4096);
                uint32_t b[8][2];
#pragma unroll
                for (int g2 = 0; g2 < 4; ++g2)
                    ldsm_x4(b[2 * g2][0], b[2 * g2 + 1][0],
                            b[2 * g2][1], b[2 * g2 + 1][1],
                            bBase[g2] + bOff + s * (2 * B_CHUNK_STRIDE));
#pragma unroll
                for (int f = 0; f < 2; ++f)
#pragma unroll
                    for (int g = 0; g < 8; ++g) {
                        asm volatile(
                            "mma.sync.aligned.m16n8k16.row.col.f32.f16.f16.f32 "
                            "{%0,%1,%2,%3}, {%4,%5,%6,%7}, {%8,%9}, {%0,%1,%2,%3};"
                            : "+f"(acc[f][g][0]), "+f"(acc[f][g][1]),
                              "+f"(acc[f][g][2]), "+f"(acc[f][g][3])
                            : "r"(a[f][0]), "r"(a[f][1]), "r"(a[f][2]), "r"(a[f][3]),
                              "r"(b[g][0]), "r"(b[g][1]));
                    }
            }
        }
        if (lane == 0) MBAR_ARRIVE(mbAfree[buf]);
        if (tid == 0) {
            const int nt = tap + NSTAGE;
            if (nt < 27) {
                const int nb = nt % NSTAGE;
                MBAR_WAIT(mbAfree[nb], (nt / NSTAGE - 1) & 1);
                MBAR_EXPECT_TX(mbArdy[nb], SMA_BYTES);
                BULK_G2S(smA_u + nb * SMA_BYTES,
                         wsrc + (size_t)nt * 2 * SMA_BYTES, SMA_BYTES, mbArdy[nb]);
            }
        }
    }

    // ---- epilogue: BN + activation + STG (__half2)
#pragma unroll
    for (int f = 0; f < 2; ++f)
#pragma unroll
        for (int r = 0; r < 2; ++r) {
            const int cg = coutBase + warpM + 16 * f + 8 * r + mr;
            const float s = gamma[cg] * rsqrtf(var[cg] + EPS);
            const float sh = beta[cg] - mean[cg] * s;
            const int gt = cg >> 6;
            const bool sg = (gt == 1) || (gt == 2);
            __half* orow = g_gates + (size_t)cg * DHW + (size_t)d * HW;
#pragma unroll
            for (int g = 0; g < 8; ++g) {
                const int n0 = warpN + 8 * g + 2 * nc;
                const int h2 = n0 >> 5, w2 = n0 & 31;
                float v0 = acc[f][g][2 * r + 0] * s + sh;
                float v1 = acc[f][g][2 * r + 1] * s + sh;
                if (sg) {
                    v0 = 0.5f * fast_tanh(0.5f * v0) + 0.5f;
                    v1 = 0.5f * fast_tanh(0.5f * v1) + 0.5f;
                } else {
                    v0 = fast_tanh(v0);
                    v1 = fast_tanh(v1);
                }
                *reinterpret_cast<__half2*>(orow + (hBase + h2) * WW + wBase + w2)
                    = __float22half2_rn(make_float2(v0, v1));
            }
        }
}

// ---------------- SRU scan over depth (vectorized 8-wide) ----------------
__global__ void sru_scan_kernel(float* __restrict__ out)
{
    const int idx = blockIdx.x * blockDim.x + threadIdx.x;
    if (idx >= CIN * (HW / 8)) return;
    const int c = idx / (HW / 8);
    const int hw8 = (idx % (HW / 8)) * 8;

    const __half* pw = g_gates + (size_t)(0 * 64 + c) * DHW + hw8;
    const __half* pf = g_gates + (size_t)(1 * 64 + c) * DHW + hw8;
    const __half* pr = g_gates + (size_t)(2 * 64 + c) * DHW + hw8;
    const __half* px = g_gates + (size_t)(3 * 64 + c) * DHW + hw8;
    float* po = out + (size_t)c * DHW + hw8;

    float C[8];
    {
        uint4 fq = *reinterpret_cast<const uint4*>(pf);
        uint4 rq = *reinterpret_cast<const uint4*>(pr);
        uint4 xq = *reinterpret_cast<const uint4*>(px);
        const __half2* f2 = (const __half2*)&fq;
        const __half2* r2 = (const __half2*)&rq;
        const __half2* x2 = (const __half2*)&xq;
        float ov[8];
#pragma unroll
        for (int q = 0; q < 4; ++q) {
            float2 fa = __half22float2(f2[q]);
            float2 ra = __half22float2(r2[q]);
            float2 xa = __half22float2(x2[q]);
            C[2 * q]     = 1.0f - fa.x;
            C[2 * q + 1] = 1.0f - fa.y;
            ov[2 * q]     = ra.x * C[2 * q]     + (1.0f - ra.x) * xa.x;
            ov[2 * q + 1] = ra.y * C[2 * q + 1] + (1.0f - ra.y) * xa.y;
        }
        reinterpret_cast<float4*>(po)[0] = make_float4(ov[0], ov[1], ov[2], ov[3]);
        reinterpret_cast<float4*>(po)[1] = make_float4(ov[4], ov[5], ov[6], ov[7]);
    }

    for (int dd = 1; dd < DD; ++dd) {
        const int off = dd * HW;
        uint4 wq = *reinterpret_cast<const uint4*>(pw + off);
        uint4 fq = *reinterpret_cast<const uint4*>(pf + off);
        uint4 rq = *reinterpret_cast<const uint4*>(pr + off);
        uint4 xq = *reinterpret_cast<const uint4*>(px + off);
        const __half2* w2 = (const __half2*)&wq;
        const __half2* f2 = (const __half2*)&fq;
        const __half2* r2 = (const __half2*)&rq;
        const __half2* x2 = (const __half2*)&xq;
        float ov[8];
#pragma unroll
        for (int q = 0; q < 4; ++q) {
            float2 wa = __half22float2(w2[q]);
            float2 fa = __half22float2(f2[q]);
            float2 ra = __half22float2(r2[q]);
            float2 xa = __half22float2(x2[q]);
            C[2 * q]     = fa.x * C[2 * q]     + (1.0f - fa.x) * wa.x;
            C[2 * q + 1] = fa.y * C[2 * q + 1] + (1.0f - fa.y) * wa.y;
            ov[2 * q]     = ra.x * C[2 * q]     + (1.0f - ra.x) * xa.x;
            ov[2 * q + 1] = ra.y * C[2 * q + 1] + (1.0f - ra.y) * xa.y;
        }
        reinterpret_cast<float4*>(po + off)[0] = make_float4(ov[0], ov[1], ov[2], ov[3]);
        reinterpret_cast<float4*>(po + off)[1] = make_float4(ov[4], ov[5], ov[6], ov[7]);
    }
}

extern "C" void kernel_launch(void* const* d_in, const int* in_sizes, int n_in,
                              void* d_out, int out_size)
{
    const float* x     = (const float*)d_in[0];
    const float* w     = (const float*)d_in[1];
    const float* gamma = (const float*)d_in[2];
    const float* beta  = (const float*)d_in[3];
    const float* mean  = (const float*)d_in[4];
    const float* var   = (const float*)d_in[5];
    float* out = (float*)d_out;

    prepass_kernel<<<dim3(XT_H, XT_D + 1), XT_W>>>(x, w);

    cudaFuncSetAttribute(conv_mma_kernel,
                         cudaFuncAttributeMaxDynamicSharedMemorySize, SMEM_TOTAL);
    dim3 grid(72, 31, 2);    // (24 h-tiles x 3 w-tiles), d, cout-groups
    conv_mma_kernel<<<grid, 256, SMEM_TOTAL>>>(gamma, beta, mean, var);

    const int scan_threads = 256;
    const int scan_total = CIN * (HW / 8);
    const int scan_blocks = (scan_total + scan_threads - 1) / scan_threads;
    sru_scan_kernel<<<scan_blocks, scan_threads>>>(out);
}